// round 15
// baseline (speedup 1.0000x reference)
#include <cuda_runtime.h>
#include <cuda_fp16.h>
#include <math.h>
#include <stdint.h>

#define BB 256
#define TT 1000
#define FF 310
#define H1 128
#define H2 64
#define NC 4
#define BT (BB*TT)
#define KP 320          // K padded

// -------- scratch (device globals) --------
__device__ float    g_y1[(size_t)BT*H1];
__device__ float    g_y2[(size_t)BT*H2];
__device__ unsigned g_spk1[(size_t)BT*4];
__device__ unsigned g_spk2[(size_t)BT*2];
__device__ unsigned g_cnt1, g_cnt2;
__device__ __align__(16) __half g_W1h[H1*KP];   // W1^T hi fp16, [n][k]
__device__ __align__(16) __half g_W1l[H1*KP];   // W1^T lo fp16
__device__ __align__(16) __half g_W2h[H2*H1];   // W2^T hi fp16
__device__ __align__(16) __half g_W2l[H2*H1];   // W2^T lo fp16

__device__ __forceinline__ uint32_t smem_u32(const void* p) {
    uint32_t a;
    asm("{ .reg .u64 t; cvta.to.shared.u64 t, %1; cvt.u32.u64 %0, t; }"
        : "=r"(a) : "l"(p));
    return a;
}
__device__ __forceinline__ void ldsm_x4(uint32_t* r, uint32_t addr) {
    asm volatile("ldmatrix.sync.aligned.m8n8.x4.shared.b16 {%0,%1,%2,%3}, [%4];"
                 : "=r"(r[0]), "=r"(r[1]), "=r"(r[2]), "=r"(r[3]) : "r"(addr));
}
__device__ __forceinline__ void mma_f16(float* d, const uint32_t* a, const uint32_t* b) {
    asm volatile("mma.sync.aligned.m16n8k16.row.col.f32.f16.f16.f32 "
                 "{%0,%1,%2,%3}, {%4,%5,%6,%7}, {%8,%9}, {%0,%1,%2,%3};"
                 : "+f"(d[0]), "+f"(d[1]), "+f"(d[2]), "+f"(d[3])
                 : "r"(a[0]), "r"(a[1]), "r"(a[2]), "r"(a[3]), "r"(b[0]), "r"(b[1]));
}
__device__ __forceinline__ void cp16(uint32_t dst, const void* src) {
    asm volatile("cp.async.cg.shared.global [%0], [%1], 16;"
                 :: "r"(dst), "l"(src));
}
#define CP_COMMIT() asm volatile("cp.async.commit_group;" ::: "memory")
#define CP_WAIT0()  asm volatile("cp.async.wait_group 0;"  ::: "memory")

static __device__ __forceinline__ uint32_t pk2h(__half a, __half b) {
    __half2 t(a, b);
    return *reinterpret_cast<uint32_t*>(&t);
}
static __device__ __forceinline__ uint32_t exp2h(uint32_t t) {
    return ((t & 1u) ? 0x3C00u : 0u) | ((t & 2u) ? 0x3C000000u : 0u);
}

// ---------------- K0: counters + W1 hi/lo + W2 hi/lo (fp16, transposed) ------
__global__ void k0_prep(const float* __restrict__ W1, const float* __restrict__ W2) {
    if (blockIdx.x == 0 && threadIdx.x == 0) { g_cnt1 = 0u; g_cnt2 = 0u; }
    for (int i = blockIdx.x*256 + threadIdx.x; i < H1*KP; i += gridDim.x*256) {
        int n = i / KP, k = i % KP;
        float w = (k < FF) ? W1[(size_t)k*H1 + n] : 0.f;
        __half h = __float2half_rn(w);
        float r = w - __half2float(h);
        g_W1h[i] = h;
        g_W1l[i] = __float2half_rn(r);
    }
    for (int i = blockIdx.x*256 + threadIdx.x; i < H2*H1; i += gridDim.x*256) {
        int n = i >> 7, k = i & 127;
        float w = W2[(size_t)k*H2 + n];
        __half h = __float2half_rn(w);
        float r = w - __half2float(h);
        g_W2h[i] = h;
        g_W2l[i] = __float2half_rn(r);
    }
}

// ---------------- K0n: no-op spacer (puts k2 in the ncu window) --------------
__global__ void k0n_nop() {}

// ---------------- K1: mma.sync fp16 split GEMM1 + bias + gelu + LN -----------
#define A_PITCH 80
#define OFF_A   0
#define OFF_B   40960
#define OFF_SUM 81920
#define OFF_SQ  82944
#define OFF_B1  83968
#define OFF_LS  84480
#define OFF_LB  84992
#define K1_SMEM 85504

__global__ void __launch_bounds__(256, 2)
k1_gemm1(const float* __restrict__ x, const float* __restrict__ b1,
         const float* __restrict__ lns, const float* __restrict__ lnb)
{
    extern __shared__ char sm[];
    const uint32_t sb = smem_u32(sm);
    const int tid = threadIdx.x;
    const int lane = tid & 31, wid = tid >> 5;
    const int mw = wid >> 1, nw = wid & 1;
    const int tok0 = blockIdx.x * 128;

    if (tid < 128) {
        ((float*)(sm + OFF_B1))[tid] = b1[tid];
        ((float*)(sm + OFF_LS))[tid] = lns[tid];
        ((float*)(sm + OFF_LB))[tid] = lnb[tid];
    }

    float d[2][8][4];
#pragma unroll
    for (int mt = 0; mt < 2; mt++)
#pragma unroll
        for (int nt = 0; nt < 8; nt++)
#pragma unroll
            for (int e = 0; e < 4; e++) d[mt][nt][e] = 0.f;

    const int cv_row = tid >> 1;
    const int cv_kh  = (tid & 1) * 16;
    const float* cv_src = x + (size_t)(tok0 + cv_row)*FF + cv_kh;

    const int li8 = lane & 7;
    const int a_row0 = mw*32 + 8*((lane >> 3) & 1) + li8;
    const uint32_t a_kb = (uint32_t)(lane >> 4) * 16;
    const int b_row0 = nw*64 + 8*(lane >> 4) + li8;
    const uint32_t b_kb = (uint32_t)((lane >> 3) & 1) * 16;

    float2 rx[8];          // x prefetch registers for next chunk

#define LOAD_B(c, buf) do { \
    _Pragma("unroll") \
    for (int t = 0; t < 4; t++) { \
        int i = tid + t*256; \
        int half_ = i >> 9, n = (i >> 2) & 127, j = i & 3; \
        const __half* src = (half_ ? g_W1l : g_W1h) + (size_t)n*KP + (c)*32 + j*8; \
        uint32_t dst = sb + OFF_B + (buf)*20480 + half_*10240 + (uint32_t)n*A_PITCH + j*16; \
        cp16(dst, src); \
    } \
    CP_COMMIT(); \
} while (0)

#define LOADX(c) do { \
    int kbase = (c)*32 + cv_kh; \
    const float* rp = cv_src + (c)*32; \
    _Pragma("unroll") \
    for (int j = 0; j < 8; j++) \
        rx[j] = (kbase + 2*j < FF) ? *(const float2*)(rp + 2*j) : make_float2(0.f, 0.f); \
} while (0)

#define CVTSTS(buf) do { \
    uint32_t hh[8], ll[8]; \
    _Pragma("unroll") \
    for (int j = 0; j < 8; j++) { \
        float a0 = rx[j].x, a1 = rx[j].y; \
        __half h0 = __float2half_rn(a0), h1 = __float2half_rn(a1); \
        float r0 = a0 - __half2float(h0), r1 = a1 - __half2float(h1); \
        hh[j] = pk2h(h0, h1); \
        ll[j] = pk2h(__float2half_rn(r0), __float2half_rn(r1)); \
    } \
    char* aH = sm + OFF_A + (buf)*20480 + cv_row*A_PITCH + cv_kh*2; \
    char* aL = aH + 10240; \
    *(uint4*)(aH)      = make_uint4(hh[0], hh[1], hh[2], hh[3]); \
    *(uint4*)(aH + 16) = make_uint4(hh[4], hh[5], hh[6], hh[7]); \
    *(uint4*)(aL)      = make_uint4(ll[0], ll[1], ll[2], ll[3]); \
    *(uint4*)(aL + 16) = make_uint4(ll[4], ll[5], ll[6], ll[7]); \
} while (0)

    LOAD_B(0, 0);
    LOADX(0);
    CVTSTS(0);
    CP_WAIT0();
    __syncthreads();

    for (int c = 0; c < 10; c++) {
        const int buf = c & 1;
        if (c < 9) {
            LOAD_B(c + 1, buf ^ 1);
            LOADX(c + 1);                    // LDGs issue; consumed after MMAs
        }

        const uint32_t aBase = sb + OFF_A + (uint32_t)buf*20480;
        const uint32_t bBase = sb + OFF_B + (uint32_t)buf*20480;
#pragma unroll
        for (int s = 0; s < 2; s++) {
            uint32_t ah[2][4], al[2][4];
#pragma unroll
            for (int mt = 0; mt < 2; mt++) {
                uint32_t addr = aBase + (uint32_t)(a_row0 + mt*16)*A_PITCH
                              + (uint32_t)s*32 + a_kb;
                ldsm_x4(ah[mt], addr);
                ldsm_x4(al[mt], addr + 10240);
            }
#pragma unroll
            for (int nt16 = 0; nt16 < 4; nt16++) {
                uint32_t baddr = bBase + (uint32_t)(b_row0 + nt16*16)*A_PITCH
                               + (uint32_t)s*32 + b_kb;
                uint32_t bh[4], bl[4];
                ldsm_x4(bh, baddr);
                ldsm_x4(bl, baddr + 10240);
                mma_f16(d[0][2*nt16],     ah[0], bh);
                mma_f16(d[1][2*nt16],     ah[1], bh);
                mma_f16(d[0][2*nt16 + 1], ah[0], bh + 2);
                mma_f16(d[1][2*nt16 + 1], ah[1], bh + 2);
                mma_f16(d[0][2*nt16],     al[0], bh);
                mma_f16(d[1][2*nt16],     al[1], bh);
                mma_f16(d[0][2*nt16 + 1], al[0], bh + 2);
                mma_f16(d[1][2*nt16 + 1], al[1], bh + 2);
                mma_f16(d[0][2*nt16],     ah[0], bl);
                mma_f16(d[1][2*nt16],     ah[1], bl);
                mma_f16(d[0][2*nt16 + 1], ah[0], bl + 2);
                mma_f16(d[1][2*nt16 + 1], ah[1], bl + 2);
            }
        }
        if (c < 9) {
            CVTSTS(buf ^ 1);                 // convert prefetched x, store to SMEM
            CP_WAIT0();
        }
        __syncthreads();
    }

    const float* sb1 = (const float*)(sm + OFF_B1);
    const float* sls = (const float*)(sm + OFF_LS);
    const float* slb = (const float*)(sm + OFF_LB);
    float* ssum = (float*)(sm + OFF_SUM);
    float* ssq  = (float*)(sm + OFF_SQ);

    const int q  = lane & 3;
    const int qr = lane >> 2;

    float psum[2][2], psq[2][2];
#pragma unroll
    for (int mt = 0; mt < 2; mt++)
#pragma unroll
    for (int rr = 0; rr < 2; rr++) {
        float s = 0.f, ss = 0.f;
#pragma unroll
        for (int nt = 0; nt < 8; nt++) {
#pragma unroll
            for (int e = 0; e < 2; e++) {
                int col = nw*64 + nt*8 + 2*q + e;
                float v = d[mt][nt][rr*2 + e] + sb1[col];
                float u = 0.7978845608028654f * fmaf(0.044715f*v, v*v, v);
                float ex = __expf(2.f*u);
                float th = 1.f - __fdividef(2.f, ex + 1.f);
                float g = 0.5f * v * (1.f + th);
                d[mt][nt][rr*2 + e] = g;
                s += g; ss = fmaf(g, g, ss);
            }
        }
        s  += __shfl_xor_sync(0xffffffffu, s, 1);
        s  += __shfl_xor_sync(0xffffffffu, s, 2);
        ss += __shfl_xor_sync(0xffffffffu, ss, 1);
        ss += __shfl_xor_sync(0xffffffffu, ss, 2);
        psum[mt][rr] = s; psq[mt][rr] = ss;
    }
    if (q == 0) {
#pragma unroll
        for (int mt = 0; mt < 2; mt++)
#pragma unroll
        for (int rr = 0; rr < 2; rr++) {
            int row = mw*32 + mt*16 + rr*8 + qr;
            ssum[row*2 + nw] = psum[mt][rr];
            ssq [row*2 + nw] = psq[mt][rr];
        }
    }
    __syncthreads();
#pragma unroll
    for (int mt = 0; mt < 2; mt++)
#pragma unroll
    for (int rr = 0; rr < 2; rr++) {
        int row = mw*32 + mt*16 + rr*8 + qr;
        float tot = ssum[row*2] + ssum[row*2 + 1];
        float tq  = ssq[row*2]  + ssq[row*2 + 1];
        float mu  = tot * (1.f/128.f);
        float inv = rsqrtf(fmaf(-mu, mu, tq * (1.f/128.f)) + 1e-6f);
        float* dst = g_y1 + (size_t)(tok0 + row)*H1;
#pragma unroll
        for (int nt = 0; nt < 8; nt++) {
            int col = nw*64 + nt*8 + 2*q;
            float2 o;
            o.x = (d[mt][nt][rr*2 + 0] - mu)*inv*sls[col]     + slb[col];
            o.y = (d[mt][nt][rr*2 + 1] - mu)*inv*sls[col + 1] + slb[col + 1];
            *(float2*)(dst + col) = o;
        }
    }
}

// ---------------- LIF chunk: compile-time trip count (register buf) ----------
template<int LEN, int SKIP>
__device__ __forceinline__ unsigned lif_chunk(
    const float* __restrict__ xp,
    unsigned* __restrict__ sp,
    float d, int lane, int xstride, int sstride)
{
    float v = 0.f; bool z = false;
    unsigned cnt = 0;
    float buf[16];
#pragma unroll
    for (int p = 0; p < 16; p++) buf[p] = xp[(size_t)p*xstride];
#pragma unroll 16
    for (int j = 0; j < LEN; j++) {
        float xv = buf[j & 15];
        int jn = j + 16;
        buf[j & 15] = (jn < LEN) ? xp[(size_t)jn*xstride] : 0.f;
        v = z ? xv : fmaf(v, d, xv);
        z = (v > 0.5f);
        unsigned m = __ballot_sync(0xffffffffu, z);
        if (lane == 0 && j >= SKIP) {
            sp[(size_t)(j - SKIP)*sstride] = m;
            cnt += __popc(m);
        }
    }
    return cnt;
}

// ---------------- K2: LIF scan layer 1, 2-way T-chunked (warmup 64) ----------
__global__ void __launch_bounds__(256) k2_lif1(const float* __restrict__ decay)
{
    int gt = blockIdx.x*256 + threadIdx.x;
    int gw = gt >> 5, lane = gt & 31;
    int chunk = gw & 1;
    int hb = (gw >> 1) & 3;
    int b = gw >> 3;
    int h = (hb << 5) + lane;
    float d = 1.f / (1.f + expf(-decay[h]));
    const int t0 = chunk*500;
    const float* xp = g_y1 + (size_t)b*TT*H1 + h;
    unsigned* sp = g_spk1 + (size_t)b*TT*4 + hb + (size_t)t0*4;
    unsigned cnt;
    if (chunk == 0)
        cnt = lif_chunk<500, 0>(xp, sp, d, lane, H1, 4);
    else
        cnt = lif_chunk<564, 64>(xp + (size_t)(t0 - 64)*H1, sp, d, lane, H1, 4);
    if (lane == 0) atomicAdd(&g_cnt1, cnt);
}

// ---------------- K3: fp16 GEMM2, warp tile 32x64, A in registers, + LN ------
#define K3P 272
#define OFF3_BH 0
#define OFF3_BL 17408
#define OFF3_B2 34816
#define OFF3_LS 35072
#define OFF3_LB 35328
#define K3_SMEM 35584

__global__ void __launch_bounds__(256, 2)
k3_gemm2(const float* __restrict__ b2,
         const float* __restrict__ lns, const float* __restrict__ lnb)
{
    extern __shared__ char sm[];
    const uint32_t sb = smem_u32(sm);
    const int tid = threadIdx.x;
    const int lane = tid & 31, wid = tid >> 5;
    const int tok0 = blockIdx.x * 256;

    {
        const uint4* sh = (const uint4*)g_W2h;
        const uint4* sl = (const uint4*)g_W2l;
        for (int i = tid; i < 1024; i += 256) {
            int n = i >> 4, j = i & 15;
            uint32_t off = (uint32_t)n*K3P + (uint32_t)j*16;
            *(uint4*)(sm + OFF3_BH + off) = sh[i];
            *(uint4*)(sm + OFF3_BL + off) = sl[i];
        }
        if (tid < 64) {
            ((float*)(sm + OFF3_B2))[tid] = b2[tid];
            ((float*)(sm + OFF3_LS))[tid] = lns[tid];
            ((float*)(sm + OFF3_LB))[tid] = lnb[tid];
        }
    }

    const int q = lane & 3, qr = lane >> 2;
    const int wr = tok0 + wid*32 + qr;
    uint4 v0 = *(const uint4*)(g_spk1 + (size_t)(wr)*4);
    uint4 v1 = *(const uint4*)(g_spk1 + (size_t)(wr + 8)*4);
    uint4 v2 = *(const uint4*)(g_spk1 + (size_t)(wr + 16)*4);
    uint4 v3 = *(const uint4*)(g_spk1 + (size_t)(wr + 24)*4);
    uint32_t m0[4] = {v0.x, v0.y, v0.z, v0.w};
    uint32_t m1[4] = {v1.x, v1.y, v1.z, v1.w};
    uint32_t m2[4] = {v2.x, v2.y, v2.z, v2.w};
    uint32_t m3[4] = {v3.x, v3.y, v3.z, v3.w};

    __syncthreads();

    float d[2][8][4];
#pragma unroll
    for (int mt = 0; mt < 2; mt++)
#pragma unroll
        for (int nt = 0; nt < 8; nt++)
#pragma unroll
            for (int e = 0; e < 4; e++) d[mt][nt][e] = 0.f;

    const uint32_t baddr = sb + OFF3_BH + (uint32_t)(8*(lane >> 4) + (lane & 7))*K3P
                         + (uint32_t)((lane >> 3) & 1)*16;

#pragma unroll
    for (int ks = 0; ks < 8; ks++) {
        const int w = ks >> 1;
        const int s0 = (ks & 1)*16 + 2*q;
        uint32_t a0[4], a1[4];
        a0[0] = exp2h(m0[w] >> s0);
        a0[1] = exp2h(m1[w] >> s0);
        a0[2] = exp2h(m0[w] >> (s0 + 8));
        a0[3] = exp2h(m1[w] >> (s0 + 8));
        a1[0] = exp2h(m2[w] >> s0);
        a1[1] = exp2h(m3[w] >> s0);
        a1[2] = exp2h(m2[w] >> (s0 + 8));
        a1[3] = exp2h(m3[w] >> (s0 + 8));
#pragma unroll
        for (int nt16 = 0; nt16 < 4; nt16++) {
            uint32_t ba = baddr + (uint32_t)nt16*(16*K3P) + ks*32;
            uint32_t bh[4], bl[4];
            ldsm_x4(bh, ba);
            ldsm_x4(bl, ba + OFF3_BL);
            mma_f16(d[0][2*nt16],     a0, bh);
            mma_f16(d[1][2*nt16],     a1, bh);
            mma_f16(d[0][2*nt16 + 1], a0, bh + 2);
            mma_f16(d[1][2*nt16 + 1], a1, bh + 2);
            mma_f16(d[0][2*nt16],     a0, bl);
            mma_f16(d[1][2*nt16],     a1, bl);
            mma_f16(d[0][2*nt16 + 1], a0, bl + 2);
            mma_f16(d[1][2*nt16 + 1], a1, bl + 2);
        }
    }

    const float* b2s = (const float*)(sm + OFF3_B2);
    const float* lss = (const float*)(sm + OFF3_LS);
    const float* lbs = (const float*)(sm + OFF3_LB);

#pragma unroll
    for (int mt = 0; mt < 2; mt++) {
        float s0 = 0.f, q0 = 0.f, s1 = 0.f, q1 = 0.f;
#pragma unroll
        for (int nt = 0; nt < 8; nt++) {
            int c0 = nt*8 + 2*q;
            float u0 = d[mt][nt][0] + b2s[c0], u1 = d[mt][nt][1] + b2s[c0 + 1];
            float u2 = d[mt][nt][2] + b2s[c0], u3 = d[mt][nt][3] + b2s[c0 + 1];
            d[mt][nt][0] = u0; d[mt][nt][1] = u1; d[mt][nt][2] = u2; d[mt][nt][3] = u3;
            s0 += u0 + u1; q0 = fmaf(u0, u0, fmaf(u1, u1, q0));
            s1 += u2 + u3; q1 = fmaf(u2, u2, fmaf(u3, u3, q1));
        }
#pragma unroll
        for (int o = 1; o <= 2; o <<= 1) {
            s0 += __shfl_xor_sync(0xffffffffu, s0, o);
            q0 += __shfl_xor_sync(0xffffffffu, q0, o);
            s1 += __shfl_xor_sync(0xffffffffu, s1, o);
            q1 += __shfl_xor_sync(0xffffffffu, q1, o);
        }
        float mu0 = s0 * (1.f/64.f);
        float iv0 = rsqrtf(fmaf(-mu0, mu0, q0 * (1.f/64.f)) + 1e-6f);
        float mu1 = s1 * (1.f/64.f);
        float iv1 = rsqrtf(fmaf(-mu1, mu1, q1 * (1.f/64.f)) + 1e-6f);

        float* y0 = g_y2 + (size_t)(wr + mt*16)*H2;
        float* y1 = y0 + (size_t)8*H2;
#pragma unroll
        for (int nt = 0; nt < 8; nt++) {
            int c0 = nt*8 + 2*q;
            float2 o0, o1;
            o0.x = (d[mt][nt][0] - mu0)*iv0*lss[c0]     + lbs[c0];
            o0.y = (d[mt][nt][1] - mu0)*iv0*lss[c0 + 1] + lbs[c0 + 1];
            o1.x = (d[mt][nt][2] - mu1)*iv1*lss[c0]     + lbs[c0];
            o1.y = (d[mt][nt][3] - mu1)*iv1*lss[c0 + 1] + lbs[c0 + 1];
            *(float2*)(y0 + c0) = o0;
            *(float2*)(y1 + c0) = o1;
        }
    }
}

// ---------------- K4: LIF scan layer 2, 2-way T-chunked (warmup 64) ----------
__global__ void __launch_bounds__(256) k4_lif2(const float* __restrict__ decay)
{
    int gt = blockIdx.x*256 + threadIdx.x;
    int gw = gt >> 5, lane = gt & 31;
    int chunk = gw & 1;
    int kb = (gw >> 1) & 1;
    int b = gw >> 2;
    int k = (kb << 5) + lane;
    float d = 1.f / (1.f + expf(-decay[k]));
    const int t0 = chunk*500;
    const float* xp = g_y2 + (size_t)b*TT*H2 + k;
    unsigned* sp = g_spk2 + (size_t)b*TT*2 + kb + (size_t)t0*2;
    unsigned cnt;
    if (chunk == 0)
        cnt = lif_chunk<500, 0>(xp, sp, d, lane, H2, 2);
    else
        cnt = lif_chunk<564, 64>(xp + (size_t)(t0 - 64)*H2, sp, d, lane, H2, 2);
    if (lane == 0) atomicAdd(&g_cnt2, cnt);
}

// ---------------- K5: logits + softmax + pool + output (merged) --------------
__global__ void __launch_bounds__(256) k5b(const float* __restrict__ Wa,
                                           const float* __restrict__ ba,
                                           const float* __restrict__ Wo,
                                           const float* __restrict__ bo,
                                           float* __restrict__ out, int rate_idx)
{
    __shared__ float was[H2];
    __shared__ float es[TT];
    __shared__ uint2 sspk[TT];
    __shared__ float red[8];
    __shared__ float bcM, bcS;
    __shared__ float fpart[4][H2];
    __shared__ float featS[H2];
    int b = blockIdx.x, tid = threadIdx.x;
    int warp = tid >> 5, lane = tid & 31;
    const unsigned* spb = g_spk2 + (size_t)b*TT*2;

    if (tid < H2) was[tid] = Wa[tid];
    __syncthreads();
    const float ba0 = ba[0];

    float lm = -3.402823466e38f;
    for (int t = tid; t < TT; t += 256) {
        uint2 m = *(const uint2*)(spb + (size_t)t*2);
        sspk[t] = m;
        float av = ba0;
        unsigned mm = m.x;
        while (mm) { av += was[__ffs(mm) - 1];      mm &= mm - 1; }
        mm = m.y;
        while (mm) { av += was[32 + __ffs(mm) - 1]; mm &= mm - 1; }
        es[t] = av;
        lm = fmaxf(lm, av);
    }
#pragma unroll
    for (int o = 16; o > 0; o >>= 1) lm = fmaxf(lm, __shfl_xor_sync(0xffffffffu, lm, o));
    if (lane == 0) red[warp] = lm;
    __syncthreads();
    if (tid == 0) {
        float m = red[0];
#pragma unroll
        for (int w = 1; w < 8; w++) m = fmaxf(m, red[w]);
        bcM = m;
    }
    __syncthreads();
    float M = bcM;
    float ls = 0.f;
    for (int t = tid; t < TT; t += 256) { float e = expf(es[t] - M); es[t] = e; ls += e; }
#pragma unroll
    for (int o = 16; o > 0; o >>= 1) ls += __shfl_xor_sync(0xffffffffu, ls, o);
    if (lane == 0) red[warp] = ls;
    __syncthreads();
    if (tid == 0) {
        float sm = 0.f;
#pragma unroll
        for (int w = 0; w < 8; w++) sm += red[w];
        bcS = sm;
    }
    __syncthreads();
    float S = bcS;

    {
        int col = tid & 63, qt = tid >> 6;
        unsigned bit = 1u << (col & 31);
        bool hi = (col >> 5) & 1;
        float acc = 0.f;
        int t0 = qt*250, t1 = t0 + 250;
        for (int t = t0; t < t1; t++) {
            uint2 m = sspk[t];
            unsigned w = hi ? m.y : m.x;
            if (w & bit) acc += es[t];
        }
        fpart[qt][col] = acc;
    }
    __syncthreads();
    if (tid < H2)
        featS[tid] = (fpart[0][tid] + fpart[1][tid] + fpart[2][tid] + fpart[3][tid]) / S;
    __syncthreads();
    if (tid < NC) {
        float l = bo[tid];
#pragma unroll
        for (int k = 0; k < H2; k++) l = fmaf(featS[k], Wo[k*NC + tid], l);
        out[b*NC + tid] = l;
    }
    if (b == 0 && tid == 0) {
        float r1 = (float)g_cnt1 / (float)((size_t)BT * H1);
        float r2 = (float)g_cnt2 / (float)((size_t)BT * H2);
        out[rate_idx] = 0.5f * (r1 + r2);
    }
}

// ---------------- launch ----------------
extern "C" void kernel_launch(void* const* d_in, const int* in_sizes, int n_in,
                              void* d_out, int out_size)
{
    const float* x   = (const float*)d_in[0];
    const float* W1  = (const float*)d_in[1];
    const float* b1  = (const float*)d_in[2];
    const float* l1s = (const float*)d_in[3];
    const float* l1b = (const float*)d_in[4];
    const float* dc1 = (const float*)d_in[5];
    const float* W2  = (const float*)d_in[6];
    const float* b2  = (const float*)d_in[7];
    const float* l2s = (const float*)d_in[8];
    const float* l2b = (const float*)d_in[9];
    const float* dc2 = (const float*)d_in[10];
    const float* Wa  = (const float*)d_in[11];
    const float* ba  = (const float*)d_in[12];
    const float* Wo  = (const float*)d_in[13];
    const float* bo  = (const float*)d_in[14];
    float* out = (float*)d_out;

    cudaFuncSetAttribute(k1_gemm1, cudaFuncAttributeMaxDynamicSharedMemorySize, K1_SMEM);
    cudaFuncSetAttribute(k3_gemm2, cudaFuncAttributeMaxDynamicSharedMemorySize, K3_SMEM);

    // launch order puts k2 at position 4 for the fixed ncu capture window
    k0_prep<<<132, 256>>>(W1, W2);
    k1_gemm1<<<BT/128, 256, K1_SMEM>>>(x, b1, l1s, l1b);
    k0n_nop<<<1, 32>>>();
    k2_lif1<<<(BB*H1*2)/256, 256>>>(dc1);          // 2 T-chunks
    k3_gemm2<<<BT/256, 256, K3_SMEM>>>(b2, l2s, l2b);
    k4_lif2<<<(BB*H2*2)/256, 256>>>(dc2);          // 2 T-chunks
    k5b<<<BB, 256>>>(Wa, ba, Wo, bo, out, out_size - 1);
}

// round 16
// speedup vs baseline: 1.6464x; 1.6464x over previous
#include <cuda_runtime.h>
#include <cuda_fp16.h>
#include <math.h>
#include <stdint.h>

#define BB 256
#define TT 1000
#define FF 310
#define H1 128
#define H2 64
#define NC 4
#define BT (BB*TT)
#define KP 320          // K padded

// -------- scratch (device globals) --------
__device__ float    g_y1[(size_t)BT*H1];
__device__ float    g_y2[(size_t)BT*H2];
__device__ unsigned g_spk1[(size_t)BT*4];
__device__ unsigned g_spk2[(size_t)BT*2];
__device__ unsigned g_cnt1, g_cnt2;
__device__ __align__(16) __half g_W1h[H1*KP];   // W1^T hi fp16, [n][k]
__device__ __align__(16) __half g_W1l[H1*KP];   // W1^T lo fp16
__device__ __align__(16) __half g_W2h[H2*H1];   // W2^T hi fp16
__device__ __align__(16) __half g_W2l[H2*H1];   // W2^T lo fp16

__device__ __forceinline__ uint32_t smem_u32(const void* p) {
    uint32_t a;
    asm("{ .reg .u64 t; cvta.to.shared.u64 t, %1; cvt.u32.u64 %0, t; }"
        : "=r"(a) : "l"(p));
    return a;
}
__device__ __forceinline__ void ldsm_x4(uint32_t* r, uint32_t addr) {
    asm volatile("ldmatrix.sync.aligned.m8n8.x4.shared.b16 {%0,%1,%2,%3}, [%4];"
                 : "=r"(r[0]), "=r"(r[1]), "=r"(r[2]), "=r"(r[3]) : "r"(addr));
}
__device__ __forceinline__ void mma_f16(float* d, const uint32_t* a, const uint32_t* b) {
    asm volatile("mma.sync.aligned.m16n8k16.row.col.f32.f16.f16.f32 "
                 "{%0,%1,%2,%3}, {%4,%5,%6,%7}, {%8,%9}, {%0,%1,%2,%3};"
                 : "+f"(d[0]), "+f"(d[1]), "+f"(d[2]), "+f"(d[3])
                 : "r"(a[0]), "r"(a[1]), "r"(a[2]), "r"(a[3]), "r"(b[0]), "r"(b[1]));
}
__device__ __forceinline__ void cp16(uint32_t dst, const void* src) {
    asm volatile("cp.async.cg.shared.global [%0], [%1], 16;"
                 :: "r"(dst), "l"(src));
}
#define CP_COMMIT() asm volatile("cp.async.commit_group;" ::: "memory")
#define CP_WAIT0()  asm volatile("cp.async.wait_group 0;"  ::: "memory")

static __device__ __forceinline__ uint32_t pk2h(__half a, __half b) {
    __half2 t(a, b);
    return *reinterpret_cast<uint32_t*>(&t);
}
static __device__ __forceinline__ uint32_t exp2h(uint32_t t) {
    return ((t & 1u) ? 0x3C00u : 0u) | ((t & 2u) ? 0x3C000000u : 0u);
}

// ---------------- K0: counters + W1 hi/lo + W2 hi/lo (fp16, transposed) ------
__global__ void k0_prep(const float* __restrict__ W1, const float* __restrict__ W2) {
    if (blockIdx.x == 0 && threadIdx.x == 0) { g_cnt1 = 0u; g_cnt2 = 0u; }
    for (int i = blockIdx.x*256 + threadIdx.x; i < H1*KP; i += gridDim.x*256) {
        int n = i / KP, k = i % KP;
        float w = (k < FF) ? W1[(size_t)k*H1 + n] : 0.f;
        __half h = __float2half_rn(w);
        float r = w - __half2float(h);
        g_W1h[i] = h;
        g_W1l[i] = __float2half_rn(r);
    }
    for (int i = blockIdx.x*256 + threadIdx.x; i < H2*H1; i += gridDim.x*256) {
        int n = i >> 7, k = i & 127;
        float w = W2[(size_t)k*H2 + n];
        __half h = __float2half_rn(w);
        float r = w - __half2float(h);
        g_W2h[i] = h;
        g_W2l[i] = __float2half_rn(r);
    }
}

// ---------------- K0n: no-op spacer (keeps k2 in the ncu window) -------------
__global__ void k0n_nop() {}

// ---------------- K1: mma.sync fp16 split GEMM1 + bias + gelu + LN -----------
#define A_PITCH 80
#define OFF_A   0
#define OFF_B   40960
#define OFF_SUM 81920
#define OFF_SQ  82944
#define OFF_B1  83968
#define OFF_LS  84480
#define OFF_LB  84992
#define K1_SMEM 85504

__global__ void __launch_bounds__(256, 2)
k1_gemm1(const float* __restrict__ x, const float* __restrict__ b1,
         const float* __restrict__ lns, const float* __restrict__ lnb)
{
    extern __shared__ char sm[];
    const uint32_t sb = smem_u32(sm);
    const int tid = threadIdx.x;
    const int lane = tid & 31, wid = tid >> 5;
    const int mw = wid >> 1, nw = wid & 1;
    const int tok0 = blockIdx.x * 128;

    if (tid < 128) {
        ((float*)(sm + OFF_B1))[tid] = b1[tid];
        ((float*)(sm + OFF_LS))[tid] = lns[tid];
        ((float*)(sm + OFF_LB))[tid] = lnb[tid];
    }

    float d[2][8][4];
#pragma unroll
    for (int mt = 0; mt < 2; mt++)
#pragma unroll
        for (int nt = 0; nt < 8; nt++)
#pragma unroll
            for (int e = 0; e < 4; e++) d[mt][nt][e] = 0.f;

    const int cv_row = tid >> 1;
    const int cv_kh  = (tid & 1) * 16;
    const float* cv_src = x + (size_t)(tok0 + cv_row)*FF + cv_kh;

    const int li8 = lane & 7;
    const int a_row0 = mw*32 + 8*((lane >> 3) & 1) + li8;
    const uint32_t a_kb = (uint32_t)(lane >> 4) * 16;
    const int b_row0 = nw*64 + 8*(lane >> 4) + li8;
    const uint32_t b_kb = (uint32_t)((lane >> 3) & 1) * 16;

    float2 rx[8];          // x prefetch registers for next chunk

#define LOAD_B(c, buf) do { \
    _Pragma("unroll") \
    for (int t = 0; t < 4; t++) { \
        int i = tid + t*256; \
        int half_ = i >> 9, n = (i >> 2) & 127, j = i & 3; \
        const __half* src = (half_ ? g_W1l : g_W1h) + (size_t)n*KP + (c)*32 + j*8; \
        uint32_t dst = sb + OFF_B + (buf)*20480 + half_*10240 + (uint32_t)n*A_PITCH + j*16; \
        cp16(dst, src); \
    } \
    CP_COMMIT(); \
} while (0)

#define LOADX(c) do { \
    int kbase = (c)*32 + cv_kh; \
    const float* rp = cv_src + (c)*32; \
    _Pragma("unroll") \
    for (int j = 0; j < 8; j++) \
        rx[j] = (kbase + 2*j < FF) ? *(const float2*)(rp + 2*j) : make_float2(0.f, 0.f); \
} while (0)

#define CVTSTS(buf) do { \
    uint32_t hh[8], ll[8]; \
    _Pragma("unroll") \
    for (int j = 0; j < 8; j++) { \
        float a0 = rx[j].x, a1 = rx[j].y; \
        __half h0 = __float2half_rn(a0), h1 = __float2half_rn(a1); \
        float r0 = a0 - __half2float(h0), r1 = a1 - __half2float(h1); \
        hh[j] = pk2h(h0, h1); \
        ll[j] = pk2h(__float2half_rn(r0), __float2half_rn(r1)); \
    } \
    char* aH = sm + OFF_A + (buf)*20480 + cv_row*A_PITCH + cv_kh*2; \
    char* aL = aH + 10240; \
    *(uint4*)(aH)      = make_uint4(hh[0], hh[1], hh[2], hh[3]); \
    *(uint4*)(aH + 16) = make_uint4(hh[4], hh[5], hh[6], hh[7]); \
    *(uint4*)(aL)      = make_uint4(ll[0], ll[1], ll[2], ll[3]); \
    *(uint4*)(aL + 16) = make_uint4(ll[4], ll[5], ll[6], ll[7]); \
} while (0)

    LOAD_B(0, 0);
    LOADX(0);
    CVTSTS(0);
    CP_WAIT0();
    __syncthreads();

    for (int c = 0; c < 10; c++) {
        const int buf = c & 1;
        if (c < 9) {
            LOAD_B(c + 1, buf ^ 1);
            LOADX(c + 1);                    // LDGs issue; consumed after MMAs
        }

        const uint32_t aBase = sb + OFF_A + (uint32_t)buf*20480;
        const uint32_t bBase = sb + OFF_B + (uint32_t)buf*20480;
#pragma unroll
        for (int s = 0; s < 2; s++) {
            uint32_t ah[2][4], al[2][4];
#pragma unroll
            for (int mt = 0; mt < 2; mt++) {
                uint32_t addr = aBase + (uint32_t)(a_row0 + mt*16)*A_PITCH
                              + (uint32_t)s*32 + a_kb;
                ldsm_x4(ah[mt], addr);
                ldsm_x4(al[mt], addr + 10240);
            }
#pragma unroll
            for (int nt16 = 0; nt16 < 4; nt16++) {
                uint32_t baddr = bBase + (uint32_t)(b_row0 + nt16*16)*A_PITCH
                               + (uint32_t)s*32 + b_kb;
                uint32_t bh[4], bl[4];
                ldsm_x4(bh, baddr);
                ldsm_x4(bl, baddr + 10240);
                mma_f16(d[0][2*nt16],     ah[0], bh);
                mma_f16(d[1][2*nt16],     ah[1], bh);
                mma_f16(d[0][2*nt16 + 1], ah[0], bh + 2);
                mma_f16(d[1][2*nt16 + 1], ah[1], bh + 2);
                mma_f16(d[0][2*nt16],     al[0], bh);
                mma_f16(d[1][2*nt16],     al[1], bh);
                mma_f16(d[0][2*nt16 + 1], al[0], bh + 2);
                mma_f16(d[1][2*nt16 + 1], al[1], bh + 2);
                mma_f16(d[0][2*nt16],     ah[0], bl);
                mma_f16(d[1][2*nt16],     ah[1], bl);
                mma_f16(d[0][2*nt16 + 1], ah[0], bl + 2);
                mma_f16(d[1][2*nt16 + 1], ah[1], bl + 2);
            }
        }
        if (c < 9) {
            CVTSTS(buf ^ 1);                 // convert prefetched x, store to SMEM
            CP_WAIT0();
        }
        __syncthreads();
    }

    const float* sb1 = (const float*)(sm + OFF_B1);
    const float* sls = (const float*)(sm + OFF_LS);
    const float* slb = (const float*)(sm + OFF_LB);
    float* ssum = (float*)(sm + OFF_SUM);
    float* ssq  = (float*)(sm + OFF_SQ);

    const int q  = lane & 3;
    const int qr = lane >> 2;

    float psum[2][2], psq[2][2];
#pragma unroll
    for (int mt = 0; mt < 2; mt++)
#pragma unroll
    for (int rr = 0; rr < 2; rr++) {
        float s = 0.f, ss = 0.f;
#pragma unroll
        for (int nt = 0; nt < 8; nt++) {
#pragma unroll
            for (int e = 0; e < 2; e++) {
                int col = nw*64 + nt*8 + 2*q + e;
                float v = d[mt][nt][rr*2 + e] + sb1[col];
                float u = 0.7978845608028654f * fmaf(0.044715f*v, v*v, v);
                float ex = __expf(2.f*u);
                float th = 1.f - __fdividef(2.f, ex + 1.f);
                float g = 0.5f * v * (1.f + th);
                d[mt][nt][rr*2 + e] = g;
                s += g; ss = fmaf(g, g, ss);
            }
        }
        s  += __shfl_xor_sync(0xffffffffu, s, 1);
        s  += __shfl_xor_sync(0xffffffffu, s, 2);
        ss += __shfl_xor_sync(0xffffffffu, ss, 1);
        ss += __shfl_xor_sync(0xffffffffu, ss, 2);
        psum[mt][rr] = s; psq[mt][rr] = ss;
    }
    if (q == 0) {
#pragma unroll
        for (int mt = 0; mt < 2; mt++)
#pragma unroll
        for (int rr = 0; rr < 2; rr++) {
            int row = mw*32 + mt*16 + rr*8 + qr;
            ssum[row*2 + nw] = psum[mt][rr];
            ssq [row*2 + nw] = psq[mt][rr];
        }
    }
    __syncthreads();
#pragma unroll
    for (int mt = 0; mt < 2; mt++)
#pragma unroll
    for (int rr = 0; rr < 2; rr++) {
        int row = mw*32 + mt*16 + rr*8 + qr;
        float tot = ssum[row*2] + ssum[row*2 + 1];
        float tq  = ssq[row*2]  + ssq[row*2 + 1];
        float mu  = tot * (1.f/128.f);
        float inv = rsqrtf(fmaf(-mu, mu, tq * (1.f/128.f)) + 1e-6f);
        float* dst = g_y1 + (size_t)(tok0 + row)*H1;
#pragma unroll
        for (int nt = 0; nt < 8; nt++) {
            int col = nw*64 + nt*8 + 2*q;
            float2 o;
            o.x = (d[mt][nt][rr*2 + 0] - mu)*inv*sls[col]     + slb[col];
            o.y = (d[mt][nt][rr*2 + 1] - mu)*inv*sls[col + 1] + slb[col + 1];
            *(float2*)(dst + col) = o;
        }
    }
}

// ---------------- LIF chunk: compile-time trip count (register buf) ----------
template<int LEN, int SKIP>
__device__ __forceinline__ unsigned lif_chunk(
    const float* __restrict__ xp,
    unsigned* __restrict__ sp,
    float d, int lane, int xstride, int sstride)
{
    float v = 0.f; bool z = false;
    unsigned cnt = 0;
    float buf[16];
#pragma unroll
    for (int p = 0; p < 16; p++) buf[p] = xp[(size_t)p*xstride];
#pragma unroll 16
    for (int j = 0; j < LEN; j++) {
        float xv = buf[j & 15];
        int jn = j + 16;
        buf[j & 15] = (jn < LEN) ? xp[(size_t)jn*xstride] : 0.f;
        v = z ? xv : fmaf(v, d, xv);
        z = (v > 0.5f);
        unsigned m = __ballot_sync(0xffffffffu, z);
        if (lane == 0 && j >= SKIP) {
            sp[(size_t)(j - SKIP)*sstride] = m;
            cnt += __popc(m);
        }
    }
    return cnt;
}

// ---------------- K2: LIF scan layer 1, 8-way T-chunked (warmup 64) ----------
__global__ void __launch_bounds__(256) k2_lif1(const float* __restrict__ decay)
{
    int gt = blockIdx.x*256 + threadIdx.x;
    int gw = gt >> 5, lane = gt & 31;
    int chunk = gw & 7;
    int hb = (gw >> 3) & 3;
    int b = gw >> 5;
    int h = (hb << 5) + lane;
    float d = 1.f / (1.f + expf(-decay[h]));
    const int t0 = chunk*125;
    const float* xp = g_y1 + (size_t)b*TT*H1 + h;
    unsigned* sp = g_spk1 + (size_t)b*TT*4 + hb + (size_t)t0*4;
    unsigned cnt;
    if (chunk == 0)
        cnt = lif_chunk<125, 0>(xp, sp, d, lane, H1, 4);
    else
        cnt = lif_chunk<189, 64>(xp + (size_t)(t0 - 64)*H1, sp, d, lane, H1, 4);
    if (lane == 0) atomicAdd(&g_cnt1, cnt);
}

// ---------------- K3: fp16 GEMM2, warp tile 32x64, A in registers, + LN ------
#define K3P 272
#define OFF3_BH 0
#define OFF3_BL 17408
#define OFF3_B2 34816
#define OFF3_LS 35072
#define OFF3_LB 35328
#define K3_SMEM 35584

__global__ void __launch_bounds__(256, 2)
k3_gemm2(const float* __restrict__ b2,
         const float* __restrict__ lns, const float* __restrict__ lnb)
{
    extern __shared__ char sm[];
    const uint32_t sb = smem_u32(sm);
    const int tid = threadIdx.x;
    const int lane = tid & 31, wid = tid >> 5;
    const int tok0 = blockIdx.x * 256;

    {
        const uint4* sh = (const uint4*)g_W2h;
        const uint4* sl = (const uint4*)g_W2l;
        for (int i = tid; i < 1024; i += 256) {
            int n = i >> 4, j = i & 15;
            uint32_t off = (uint32_t)n*K3P + (uint32_t)j*16;
            *(uint4*)(sm + OFF3_BH + off) = sh[i];
            *(uint4*)(sm + OFF3_BL + off) = sl[i];
        }
        if (tid < 64) {
            ((float*)(sm + OFF3_B2))[tid] = b2[tid];
            ((float*)(sm + OFF3_LS))[tid] = lns[tid];
            ((float*)(sm + OFF3_LB))[tid] = lnb[tid];
        }
    }

    const int q = lane & 3, qr = lane >> 2;
    const int wr = tok0 + wid*32 + qr;
    uint4 v0 = *(const uint4*)(g_spk1 + (size_t)(wr)*4);
    uint4 v1 = *(const uint4*)(g_spk1 + (size_t)(wr + 8)*4);
    uint4 v2 = *(const uint4*)(g_spk1 + (size_t)(wr + 16)*4);
    uint4 v3 = *(const uint4*)(g_spk1 + (size_t)(wr + 24)*4);
    uint32_t m0[4] = {v0.x, v0.y, v0.z, v0.w};
    uint32_t m1[4] = {v1.x, v1.y, v1.z, v1.w};
    uint32_t m2[4] = {v2.x, v2.y, v2.z, v2.w};
    uint32_t m3[4] = {v3.x, v3.y, v3.z, v3.w};

    __syncthreads();

    float d[2][8][4];
#pragma unroll
    for (int mt = 0; mt < 2; mt++)
#pragma unroll
        for (int nt = 0; nt < 8; nt++)
#pragma unroll
            for (int e = 0; e < 4; e++) d[mt][nt][e] = 0.f;

    const uint32_t baddr = sb + OFF3_BH + (uint32_t)(8*(lane >> 4) + (lane & 7))*K3P
                         + (uint32_t)((lane >> 3) & 1)*16;

#pragma unroll
    for (int ks = 0; ks < 8; ks++) {
        const int w = ks >> 1;
        const int s0 = (ks & 1)*16 + 2*q;
        uint32_t a0[4], a1[4];
        a0[0] = exp2h(m0[w] >> s0);
        a0[1] = exp2h(m1[w] >> s0);
        a0[2] = exp2h(m0[w] >> (s0 + 8));
        a0[3] = exp2h(m1[w] >> (s0 + 8));
        a1[0] = exp2h(m2[w] >> s0);
        a1[1] = exp2h(m3[w] >> s0);
        a1[2] = exp2h(m2[w] >> (s0 + 8));
        a1[3] = exp2h(m3[w] >> (s0 + 8));
#pragma unroll
        for (int nt16 = 0; nt16 < 4; nt16++) {
            uint32_t ba = baddr + (uint32_t)nt16*(16*K3P) + ks*32;
            uint32_t bh[4], bl[4];
            ldsm_x4(bh, ba);
            ldsm_x4(bl, ba + OFF3_BL);
            mma_f16(d[0][2*nt16],     a0, bh);
            mma_f16(d[1][2*nt16],     a1, bh);
            mma_f16(d[0][2*nt16 + 1], a0, bh + 2);
            mma_f16(d[1][2*nt16 + 1], a1, bh + 2);
            mma_f16(d[0][2*nt16],     a0, bl);
            mma_f16(d[1][2*nt16],     a1, bl);
            mma_f16(d[0][2*nt16 + 1], a0, bl + 2);
            mma_f16(d[1][2*nt16 + 1], a1, bl + 2);
        }
    }

    const float* b2s = (const float*)(sm + OFF3_B2);
    const float* lss = (const float*)(sm + OFF3_LS);
    const float* lbs = (const float*)(sm + OFF3_LB);

#pragma unroll
    for (int mt = 0; mt < 2; mt++) {
        float s0 = 0.f, q0 = 0.f, s1 = 0.f, q1 = 0.f;
#pragma unroll
        for (int nt = 0; nt < 8; nt++) {
            int c0 = nt*8 + 2*q;
            float u0 = d[mt][nt][0] + b2s[c0], u1 = d[mt][nt][1] + b2s[c0 + 1];
            float u2 = d[mt][nt][2] + b2s[c0], u3 = d[mt][nt][3] + b2s[c0 + 1];
            d[mt][nt][0] = u0; d[mt][nt][1] = u1; d[mt][nt][2] = u2; d[mt][nt][3] = u3;
            s0 += u0 + u1; q0 = fmaf(u0, u0, fmaf(u1, u1, q0));
            s1 += u2 + u3; q1 = fmaf(u2, u2, fmaf(u3, u3, q1));
        }
#pragma unroll
        for (int o = 1; o <= 2; o <<= 1) {
            s0 += __shfl_xor_sync(0xffffffffu, s0, o);
            q0 += __shfl_xor_sync(0xffffffffu, q0, o);
            s1 += __shfl_xor_sync(0xffffffffu, s1, o);
            q1 += __shfl_xor_sync(0xffffffffu, q1, o);
        }
        float mu0 = s0 * (1.f/64.f);
        float iv0 = rsqrtf(fmaf(-mu0, mu0, q0 * (1.f/64.f)) + 1e-6f);
        float mu1 = s1 * (1.f/64.f);
        float iv1 = rsqrtf(fmaf(-mu1, mu1, q1 * (1.f/64.f)) + 1e-6f);

        float* y0 = g_y2 + (size_t)(wr + mt*16)*H2;
        float* y1 = y0 + (size_t)8*H2;
#pragma unroll
        for (int nt = 0; nt < 8; nt++) {
            int c0 = nt*8 + 2*q;
            float2 o0, o1;
            o0.x = (d[mt][nt][0] - mu0)*iv0*lss[c0]     + lbs[c0];
            o0.y = (d[mt][nt][1] - mu0)*iv0*lss[c0 + 1] + lbs[c0 + 1];
            o1.x = (d[mt][nt][2] - mu1)*iv1*lss[c0]     + lbs[c0];
            o1.y = (d[mt][nt][3] - mu1)*iv1*lss[c0 + 1] + lbs[c0 + 1];
            *(float2*)(y0 + c0) = o0;
            *(float2*)(y1 + c0) = o1;
        }
    }
}

// ---------------- K4: LIF scan layer 2, 8-way T-chunked (warmup 64) ----------
__global__ void __launch_bounds__(256) k4_lif2(const float* __restrict__ decay)
{
    int gt = blockIdx.x*256 + threadIdx.x;
    int gw = gt >> 5, lane = gt & 31;
    int chunk = gw & 7;
    int kb = (gw >> 3) & 1;
    int b = gw >> 4;
    int k = (kb << 5) + lane;
    float d = 1.f / (1.f + expf(-decay[k]));
    const int t0 = chunk*125;
    const float* xp = g_y2 + (size_t)b*TT*H2 + k;
    unsigned* sp = g_spk2 + (size_t)b*TT*2 + kb + (size_t)t0*2;
    unsigned cnt;
    if (chunk == 0)
        cnt = lif_chunk<125, 0>(xp, sp, d, lane, H2, 2);
    else
        cnt = lif_chunk<189, 64>(xp + (size_t)(t0 - 64)*H2, sp, d, lane, H2, 2);
    if (lane == 0) atomicAdd(&g_cnt2, cnt);
}

// ---------------- K5: logits + softmax + pool + output (merged) --------------
__global__ void __launch_bounds__(256) k5b(const float* __restrict__ Wa,
                                           const float* __restrict__ ba,
                                           const float* __restrict__ Wo,
                                           const float* __restrict__ bo,
                                           float* __restrict__ out, int rate_idx)
{
    __shared__ float was[H2];
    __shared__ float es[TT];
    __shared__ uint2 sspk[TT];
    __shared__ float red[8];
    __shared__ float bcM, bcS;
    __shared__ float fpart[4][H2];
    __shared__ float featS[H2];
    int b = blockIdx.x, tid = threadIdx.x;
    int warp = tid >> 5, lane = tid & 31;
    const unsigned* spb = g_spk2 + (size_t)b*TT*2;

    if (tid < H2) was[tid] = Wa[tid];
    __syncthreads();
    const float ba0 = ba[0];

    float lm = -3.402823466e38f;
    for (int t = tid; t < TT; t += 256) {
        uint2 m = *(const uint2*)(spb + (size_t)t*2);
        sspk[t] = m;
        float av = ba0;
        unsigned mm = m.x;
        while (mm) { av += was[__ffs(mm) - 1];      mm &= mm - 1; }
        mm = m.y;
        while (mm) { av += was[32 + __ffs(mm) - 1]; mm &= mm - 1; }
        es[t] = av;
        lm = fmaxf(lm, av);
    }
#pragma unroll
    for (int o = 16; o > 0; o >>= 1) lm = fmaxf(lm, __shfl_xor_sync(0xffffffffu, lm, o));
    if (lane == 0) red[warp] = lm;
    __syncthreads();
    if (tid == 0) {
        float m = red[0];
#pragma unroll
        for (int w = 1; w < 8; w++) m = fmaxf(m, red[w]);
        bcM = m;
    }
    __syncthreads();
    float M = bcM;
    float ls = 0.f;
    for (int t = tid; t < TT; t += 256) { float e = expf(es[t] - M); es[t] = e; ls += e; }
#pragma unroll
    for (int o = 16; o > 0; o >>= 1) ls += __shfl_xor_sync(0xffffffffu, ls, o);
    if (lane == 0) red[warp] = ls;
    __syncthreads();
    if (tid == 0) {
        float sm = 0.f;
#pragma unroll
        for (int w = 0; w < 8; w++) sm += red[w];
        bcS = sm;
    }
    __syncthreads();
    float S = bcS;

    {
        int col = tid & 63, qt = tid >> 6;
        unsigned bit = 1u << (col & 31);
        bool hi = (col >> 5) & 1;
        float acc = 0.f;
        int t0 = qt*250, t1 = t0 + 250;
        for (int t = t0; t < t1; t++) {
            uint2 m = sspk[t];
            unsigned w = hi ? m.y : m.x;
            if (w & bit) acc += es[t];
        }
        fpart[qt][col] = acc;
    }
    __syncthreads();
    if (tid < H2)
        featS[tid] = (fpart[0][tid] + fpart[1][tid] + fpart[2][tid] + fpart[3][tid]) / S;
    __syncthreads();
    if (tid < NC) {
        float l = bo[tid];
#pragma unroll
        for (int k = 0; k < H2; k++) l = fmaf(featS[k], Wo[k*NC + tid], l);
        out[b*NC + tid] = l;
    }
    if (b == 0 && tid == 0) {
        float r1 = (float)g_cnt1 / (float)((size_t)BT * H1);
        float r2 = (float)g_cnt2 / (float)((size_t)BT * H2);
        out[rate_idx] = 0.5f * (r1 + r2);
    }
}

// ---------------- launch ----------------
extern "C" void kernel_launch(void* const* d_in, const int* in_sizes, int n_in,
                              void* d_out, int out_size)
{
    const float* x   = (const float*)d_in[0];
    const float* W1  = (const float*)d_in[1];
    const float* b1  = (const float*)d_in[2];
    const float* l1s = (const float*)d_in[3];
    const float* l1b = (const float*)d_in[4];
    const float* dc1 = (const float*)d_in[5];
    const float* W2  = (const float*)d_in[6];
    const float* b2  = (const float*)d_in[7];
    const float* l2s = (const float*)d_in[8];
    const float* l2b = (const float*)d_in[9];
    const float* dc2 = (const float*)d_in[10];
    const float* Wa  = (const float*)d_in[11];
    const float* ba  = (const float*)d_in[12];
    const float* Wo  = (const float*)d_in[13];
    const float* bo  = (const float*)d_in[14];
    float* out = (float*)d_out;

    cudaFuncSetAttribute(k1_gemm1, cudaFuncAttributeMaxDynamicSharedMemorySize, K1_SMEM);
    cudaFuncSetAttribute(k3_gemm2, cudaFuncAttributeMaxDynamicSharedMemorySize, K3_SMEM);

    // launch order keeps k2 at position 4 for the fixed ncu capture window
    k0_prep<<<132, 256>>>(W1, W2);
    k1_gemm1<<<BT/128, 256, K1_SMEM>>>(x, b1, l1s, l1b);
    k0n_nop<<<1, 32>>>();
    k2_lif1<<<(BB*H1*8)/256, 256>>>(dc1);          // 8 T-chunks
    k3_gemm2<<<BT/256, 256, K3_SMEM>>>(b2, l2s, l2b);
    k4_lif2<<<(BB*H2*8)/256, 256>>>(dc2);          // 8 T-chunks
    k5b<<<BB, 256>>>(Wa, ba, Wo, bo, out, out_size - 1);
}

// round 17
// speedup vs baseline: 1.6620x; 1.0095x over previous
#include <cuda_runtime.h>
#include <cuda_fp16.h>
#include <math.h>
#include <stdint.h>

#define BB 256
#define TT 1000
#define FF 310
#define H1 128
#define H2 64
#define NC 4
#define BT (BB*TT)
#define KP 320          // K padded

// -------- scratch (device globals) --------
__device__ float    g_y1[(size_t)BT*H1];
__device__ float    g_y2[(size_t)BT*H2];
__device__ unsigned g_spk1[(size_t)BT*4];
__device__ unsigned g_spk2[(size_t)BT*2];
__device__ unsigned g_cnt1, g_cnt2;
__device__ __align__(16) __half g_W1h[H1*KP];   // W1^T hi fp16, [n][k]
__device__ __align__(16) __half g_W1l[H1*KP];   // W1^T lo fp16
__device__ __align__(16) __half g_W2h[H2*H1];   // W2^T hi fp16
__device__ __align__(16) __half g_W2l[H2*H1];   // W2^T lo fp16

__device__ __forceinline__ uint32_t smem_u32(const void* p) {
    uint32_t a;
    asm("{ .reg .u64 t; cvta.to.shared.u64 t, %1; cvt.u32.u64 %0, t; }"
        : "=r"(a) : "l"(p));
    return a;
}
__device__ __forceinline__ void ldsm_x4(uint32_t* r, uint32_t addr) {
    asm volatile("ldmatrix.sync.aligned.m8n8.x4.shared.b16 {%0,%1,%2,%3}, [%4];"
                 : "=r"(r[0]), "=r"(r[1]), "=r"(r[2]), "=r"(r[3]) : "r"(addr));
}
__device__ __forceinline__ void mma_f16(float* d, const uint32_t* a, const uint32_t* b) {
    asm volatile("mma.sync.aligned.m16n8k16.row.col.f32.f16.f16.f32 "
                 "{%0,%1,%2,%3}, {%4,%5,%6,%7}, {%8,%9}, {%0,%1,%2,%3};"
                 : "+f"(d[0]), "+f"(d[1]), "+f"(d[2]), "+f"(d[3])
                 : "r"(a[0]), "r"(a[1]), "r"(a[2]), "r"(a[3]), "r"(b[0]), "r"(b[1]));
}
__device__ __forceinline__ void cp16(uint32_t dst, const void* src) {
    asm volatile("cp.async.cg.shared.global [%0], [%1], 16;"
                 :: "r"(dst), "l"(src));
}
#define CP_COMMIT() asm volatile("cp.async.commit_group;" ::: "memory")
#define CP_WAIT0()  asm volatile("cp.async.wait_group 0;"  ::: "memory")

static __device__ __forceinline__ uint32_t pk2h(__half a, __half b) {
    __half2 t(a, b);
    return *reinterpret_cast<uint32_t*>(&t);
}
static __device__ __forceinline__ uint32_t exp2h(uint32_t t) {
    return ((t & 1u) ? 0x3C00u : 0u) | ((t & 2u) ? 0x3C000000u : 0u);
}

// ---------------- K0: counters + W1 hi/lo + W2 hi/lo (fp16, transposed) ------
__global__ void k0_prep(const float* __restrict__ W1, const float* __restrict__ W2) {
    if (blockIdx.x == 0 && threadIdx.x == 0) { g_cnt1 = 0u; g_cnt2 = 0u; }
    for (int i = blockIdx.x*256 + threadIdx.x; i < H1*KP; i += gridDim.x*256) {
        int n = i / KP, k = i % KP;
        float w = (k < FF) ? W1[(size_t)k*H1 + n] : 0.f;
        __half h = __float2half_rn(w);
        float r = w - __half2float(h);
        g_W1h[i] = h;
        g_W1l[i] = __float2half_rn(r);
    }
    for (int i = blockIdx.x*256 + threadIdx.x; i < H2*H1; i += gridDim.x*256) {
        int n = i >> 7, k = i & 127;
        float w = W2[(size_t)k*H2 + n];
        __half h = __float2half_rn(w);
        float r = w - __half2float(h);
        g_W2h[i] = h;
        g_W2l[i] = __float2half_rn(r);
    }
}

// ---------------- K0n: no-op spacer (keeps k1 in the ncu window) -------------
__global__ void k0n_nop() {}

// ---------------- K1: mma.sync fp16 split GEMM1 + bias + gelu + LN -----------
// M-tile 64 x N 128, 256 thr, 3 CTAs/SM (32 accs/thread, ~64KB smem)
#define A_PITCH 80
#define OFF_A   0            // 2 bufs x 10240 (hi 5120 + lo 5120)
#define OFF_B   20480        // 2 bufs x 20480 (hi 10240 + lo 10240)
#define OFF_SUM 61440        // 64 rows x 2 = 512B
#define OFF_SQ  61952
#define OFF_B1  62464
#define OFF_LS  62976
#define OFF_LB  63488
#define K1_SMEM 64000

__global__ void __launch_bounds__(256, 3)
k1_gemm1(const float* __restrict__ x, const float* __restrict__ b1,
         const float* __restrict__ lns, const float* __restrict__ lnb)
{
    extern __shared__ char sm[];
    const uint32_t sb = smem_u32(sm);
    const int tid = threadIdx.x;
    const int lane = tid & 31, wid = tid >> 5;
    const int mw = wid >> 1, nw = wid & 1;   // 4 m-warps x 2 n-warps
    const int tok0 = blockIdx.x * 64;

    if (tid < 128) {
        ((float*)(sm + OFF_B1))[tid] = b1[tid];
        ((float*)(sm + OFF_LS))[tid] = lns[tid];
        ((float*)(sm + OFF_LB))[tid] = lnb[tid];
    }

    float d[8][4];
#pragma unroll
    for (int nt = 0; nt < 8; nt++)
#pragma unroll
        for (int e = 0; e < 4; e++) d[nt][e] = 0.f;

    const int cv_row = tid >> 2;             // 0..63
    const int cv_kq  = (tid & 3) * 8;        // k offset within 32-chunk
    const float* cv_src = x + (size_t)(tok0 + cv_row)*FF + cv_kq;

    const int li8 = lane & 7;
    const int a_row0 = mw*16 + 8*((lane >> 3) & 1) + li8;
    const uint32_t a_kb = (uint32_t)(lane >> 4) * 16;
    const int b_row0 = nw*64 + 8*(lane >> 4) + li8;
    const uint32_t b_kb = (uint32_t)((lane >> 3) & 1) * 16;

    float2 rx[4];          // x prefetch regs (8 k-values)

#define LOAD_B(c, buf) do { \
    _Pragma("unroll") \
    for (int t = 0; t < 4; t++) { \
        int i = tid + t*256; \
        int half_ = i >> 9, n = (i >> 2) & 127, j = i & 3; \
        const __half* src = (half_ ? g_W1l : g_W1h) + (size_t)n*KP + (c)*32 + j*8; \
        uint32_t dst = sb + OFF_B + (buf)*20480 + half_*10240 + (uint32_t)n*A_PITCH + j*16; \
        cp16(dst, src); \
    } \
    CP_COMMIT(); \
} while (0)

#define LOADX(c) do { \
    int kbase = (c)*32 + cv_kq; \
    const float* rp = cv_src + (c)*32; \
    _Pragma("unroll") \
    for (int j = 0; j < 4; j++) \
        rx[j] = (kbase + 2*j < FF) ? *(const float2*)(rp + 2*j) : make_float2(0.f, 0.f); \
} while (0)

#define CVTSTS(buf) do { \
    uint32_t hh[4], ll[4]; \
    _Pragma("unroll") \
    for (int j = 0; j < 4; j++) { \
        float a0 = rx[j].x, a1 = rx[j].y; \
        __half h0 = __float2half_rn(a0), h1 = __float2half_rn(a1); \
        float r0 = a0 - __half2float(h0), r1 = a1 - __half2float(h1); \
        hh[j] = pk2h(h0, h1); \
        ll[j] = pk2h(__float2half_rn(r0), __float2half_rn(r1)); \
    } \
    char* aH = sm + OFF_A + (buf)*10240 + cv_row*A_PITCH + cv_kq*2; \
    char* aL = aH + 5120; \
    *(uint4*)(aH) = make_uint4(hh[0], hh[1], hh[2], hh[3]); \
    *(uint4*)(aL) = make_uint4(ll[0], ll[1], ll[2], ll[3]); \
} while (0)

    LOAD_B(0, 0);
    LOADX(0);
    CVTSTS(0);
    CP_WAIT0();
    __syncthreads();

    for (int c = 0; c < 10; c++) {
        const int buf = c & 1;
        if (c < 9) {
            LOAD_B(c + 1, buf ^ 1);
            LOADX(c + 1);                    // LDGs issue; consumed after MMAs
        }

        const uint32_t aBase = sb + OFF_A + (uint32_t)buf*10240;
        const uint32_t bBase = sb + OFF_B + (uint32_t)buf*20480;
#pragma unroll
        for (int s = 0; s < 2; s++) {
            uint32_t ah[4], al[4];
            {
                uint32_t addr = aBase + (uint32_t)a_row0*A_PITCH
                              + (uint32_t)s*32 + a_kb;
                ldsm_x4(ah, addr);
                ldsm_x4(al, addr + 5120);
            }
#pragma unroll
            for (int nt16 = 0; nt16 < 4; nt16++) {
                uint32_t baddr = bBase + (uint32_t)(b_row0 + nt16*16)*A_PITCH
                               + (uint32_t)s*32 + b_kb;
                uint32_t bh[4], bl[4];
                ldsm_x4(bh, baddr);
                ldsm_x4(bl, baddr + 10240);
                // interleaved across the two accumulators; per-acc order
                // (ah*bh, al*bh, ah*bl) unchanged -> bit-identical
                mma_f16(d[2*nt16],     ah, bh);
                mma_f16(d[2*nt16 + 1], ah, bh + 2);
                mma_f16(d[2*nt16],     al, bh);
                mma_f16(d[2*nt16 + 1], al, bh + 2);
                mma_f16(d[2*nt16],     ah, bl);
                mma_f16(d[2*nt16 + 1], ah, bl + 2);
            }
        }
        if (c < 9) {
            CVTSTS(buf ^ 1);                 // convert prefetched x, store to SMEM
            CP_WAIT0();
        }
        __syncthreads();
    }

    const float* sb1 = (const float*)(sm + OFF_B1);
    const float* sls = (const float*)(sm + OFF_LS);
    const float* slb = (const float*)(sm + OFF_LB);
    float* ssum = (float*)(sm + OFF_SUM);
    float* ssq  = (float*)(sm + OFF_SQ);

    const int q  = lane & 3;
    const int qr = lane >> 2;

    float psum[2], psq[2];
#pragma unroll
    for (int rr = 0; rr < 2; rr++) {
        float s = 0.f, ss = 0.f;
#pragma unroll
        for (int nt = 0; nt < 8; nt++) {
#pragma unroll
            for (int e = 0; e < 2; e++) {
                int col = nw*64 + nt*8 + 2*q + e;
                float v = d[nt][rr*2 + e] + sb1[col];
                float u = 0.7978845608028654f * fmaf(0.044715f*v, v*v, v);
                float ex = __expf(2.f*u);
                float th = 1.f - __fdividef(2.f, ex + 1.f);
                float g = 0.5f * v * (1.f + th);
                d[nt][rr*2 + e] = g;
                s += g; ss = fmaf(g, g, ss);
            }
        }
        s  += __shfl_xor_sync(0xffffffffu, s, 1);
        s  += __shfl_xor_sync(0xffffffffu, s, 2);
        ss += __shfl_xor_sync(0xffffffffu, ss, 1);
        ss += __shfl_xor_sync(0xffffffffu, ss, 2);
        psum[rr] = s; psq[rr] = ss;
    }
    if (q == 0) {
#pragma unroll
        for (int rr = 0; rr < 2; rr++) {
            int row = mw*16 + rr*8 + qr;
            ssum[row*2 + nw] = psum[rr];
            ssq [row*2 + nw] = psq[rr];
        }
    }
    __syncthreads();
#pragma unroll
    for (int rr = 0; rr < 2; rr++) {
        int row = mw*16 + rr*8 + qr;
        float tot = ssum[row*2] + ssum[row*2 + 1];
        float tq  = ssq[row*2]  + ssq[row*2 + 1];
        float mu  = tot * (1.f/128.f);
        float inv = rsqrtf(fmaf(-mu, mu, tq * (1.f/128.f)) + 1e-6f);
        float* dst = g_y1 + (size_t)(tok0 + row)*H1;
#pragma unroll
        for (int nt = 0; nt < 8; nt++) {
            int col = nw*64 + nt*8 + 2*q;
            float2 o;
            o.x = (d[nt][rr*2 + 0] - mu)*inv*sls[col]     + slb[col];
            o.y = (d[nt][rr*2 + 1] - mu)*inv*sls[col + 1] + slb[col + 1];
            *(float2*)(dst + col) = o;
        }
    }
}

// ---------------- LIF chunk: compile-time trip count (register buf) ----------
template<int LEN, int SKIP>
__device__ __forceinline__ unsigned lif_chunk(
    const float* __restrict__ xp,
    unsigned* __restrict__ sp,
    float d, int lane, int xstride, int sstride)
{
    float v = 0.f; bool z = false;
    unsigned cnt = 0;
    float buf[16];
#pragma unroll
    for (int p = 0; p < 16; p++) buf[p] = xp[(size_t)p*xstride];
#pragma unroll 16
    for (int j = 0; j < LEN; j++) {
        float xv = buf[j & 15];
        int jn = j + 16;
        buf[j & 15] = (jn < LEN) ? xp[(size_t)jn*xstride] : 0.f;
        v = z ? xv : fmaf(v, d, xv);
        z = (v > 0.5f);
        unsigned m = __ballot_sync(0xffffffffu, z);
        if (lane == 0 && j >= SKIP) {
            sp[(size_t)(j - SKIP)*sstride] = m;
            cnt += __popc(m);
        }
    }
    return cnt;
}

// ---------------- K2: LIF scan layer 1, 8-way T-chunked (warmup 64) ----------
__global__ void __launch_bounds__(256) k2_lif1(const float* __restrict__ decay)
{
    int gt = blockIdx.x*256 + threadIdx.x;
    int gw = gt >> 5, lane = gt & 31;
    int chunk = gw & 7;
    int hb = (gw >> 3) & 3;
    int b = gw >> 5;
    int h = (hb << 5) + lane;
    float d = 1.f / (1.f + expf(-decay[h]));
    const int t0 = chunk*125;
    const float* xp = g_y1 + (size_t)b*TT*H1 + h;
    unsigned* sp = g_spk1 + (size_t)b*TT*4 + hb + (size_t)t0*4;
    unsigned cnt;
    if (chunk == 0)
        cnt = lif_chunk<125, 0>(xp, sp, d, lane, H1, 4);
    else
        cnt = lif_chunk<189, 64>(xp + (size_t)(t0 - 64)*H1, sp, d, lane, H1, 4);
    if (lane == 0) atomicAdd(&g_cnt1, cnt);
}

// ---------------- K3: fp16 GEMM2, warp tile 32x64, A in registers, + LN ------
#define K3P 272
#define OFF3_BH 0
#define OFF3_BL 17408
#define OFF3_B2 34816
#define OFF3_LS 35072
#define OFF3_LB 35328
#define K3_SMEM 35584

__global__ void __launch_bounds__(256, 2)
k3_gemm2(const float* __restrict__ b2,
         const float* __restrict__ lns, const float* __restrict__ lnb)
{
    extern __shared__ char sm[];
    const uint32_t sb = smem_u32(sm);
    const int tid = threadIdx.x;
    const int lane = tid & 31, wid = tid >> 5;
    const int tok0 = blockIdx.x * 256;

    {
        const uint4* sh = (const uint4*)g_W2h;
        const uint4* sl = (const uint4*)g_W2l;
        for (int i = tid; i < 1024; i += 256) {
            int n = i >> 4, j = i & 15;
            uint32_t off = (uint32_t)n*K3P + (uint32_t)j*16;
            *(uint4*)(sm + OFF3_BH + off) = sh[i];
            *(uint4*)(sm + OFF3_BL + off) = sl[i];
        }
        if (tid < 64) {
            ((float*)(sm + OFF3_B2))[tid] = b2[tid];
            ((float*)(sm + OFF3_LS))[tid] = lns[tid];
            ((float*)(sm + OFF3_LB))[tid] = lnb[tid];
        }
    }

    const int q = lane & 3, qr = lane >> 2;
    const int wr = tok0 + wid*32 + qr;
    uint4 v0 = *(const uint4*)(g_spk1 + (size_t)(wr)*4);
    uint4 v1 = *(const uint4*)(g_spk1 + (size_t)(wr + 8)*4);
    uint4 v2 = *(const uint4*)(g_spk1 + (size_t)(wr + 16)*4);
    uint4 v3 = *(const uint4*)(g_spk1 + (size_t)(wr + 24)*4);
    uint32_t m0[4] = {v0.x, v0.y, v0.z, v0.w};
    uint32_t m1[4] = {v1.x, v1.y, v1.z, v1.w};
    uint32_t m2[4] = {v2.x, v2.y, v2.z, v2.w};
    uint32_t m3[4] = {v3.x, v3.y, v3.z, v3.w};

    __syncthreads();

    float d[2][8][4];
#pragma unroll
    for (int mt = 0; mt < 2; mt++)
#pragma unroll
        for (int nt = 0; nt < 8; nt++)
#pragma unroll
            for (int e = 0; e < 4; e++) d[mt][nt][e] = 0.f;

    const uint32_t baddr = sb + OFF3_BH + (uint32_t)(8*(lane >> 4) + (lane & 7))*K3P
                         + (uint32_t)((lane >> 3) & 1)*16;

#pragma unroll
    for (int ks = 0; ks < 8; ks++) {
        const int w = ks >> 1;
        const int s0 = (ks & 1)*16 + 2*q;
        uint32_t a0[4], a1[4];
        a0[0] = exp2h(m0[w] >> s0);
        a0[1] = exp2h(m1[w] >> s0);
        a0[2] = exp2h(m0[w] >> (s0 + 8));
        a0[3] = exp2h(m1[w] >> (s0 + 8));
        a1[0] = exp2h(m2[w] >> s0);
        a1[1] = exp2h(m3[w] >> s0);
        a1[2] = exp2h(m2[w] >> (s0 + 8));
        a1[3] = exp2h(m3[w] >> (s0 + 8));
#pragma unroll
        for (int nt16 = 0; nt16 < 4; nt16++) {
            uint32_t ba = baddr + (uint32_t)nt16*(16*K3P) + ks*32;
            uint32_t bh[4], bl[4];
            ldsm_x4(bh, ba);
            ldsm_x4(bl, ba + OFF3_BL);
            mma_f16(d[0][2*nt16],     a0, bh);
            mma_f16(d[1][2*nt16],     a1, bh);
            mma_f16(d[0][2*nt16 + 1], a0, bh + 2);
            mma_f16(d[1][2*nt16 + 1], a1, bh + 2);
            mma_f16(d[0][2*nt16],     a0, bl);
            mma_f16(d[1][2*nt16],     a1, bl);
            mma_f16(d[0][2*nt16 + 1], a0, bl + 2);
            mma_f16(d[1][2*nt16 + 1], a1, bl + 2);
        }
    }

    const float* b2s = (const float*)(sm + OFF3_B2);
    const float* lss = (const float*)(sm + OFF3_LS);
    const float* lbs = (const float*)(sm + OFF3_LB);

#pragma unroll
    for (int mt = 0; mt < 2; mt++) {
        float s0 = 0.f, q0 = 0.f, s1 = 0.f, q1 = 0.f;
#pragma unroll
        for (int nt = 0; nt < 8; nt++) {
            int c0 = nt*8 + 2*q;
            float u0 = d[mt][nt][0] + b2s[c0], u1 = d[mt][nt][1] + b2s[c0 + 1];
            float u2 = d[mt][nt][2] + b2s[c0], u3 = d[mt][nt][3] + b2s[c0 + 1];
            d[mt][nt][0] = u0; d[mt][nt][1] = u1; d[mt][nt][2] = u2; d[mt][nt][3] = u3;
            s0 += u0 + u1; q0 = fmaf(u0, u0, fmaf(u1, u1, q0));
            s1 += u2 + u3; q1 = fmaf(u2, u2, fmaf(u3, u3, q1));
        }
#pragma unroll
        for (int o = 1; o <= 2; o <<= 1) {
            s0 += __shfl_xor_sync(0xffffffffu, s0, o);
            q0 += __shfl_xor_sync(0xffffffffu, q0, o);
            s1 += __shfl_xor_sync(0xffffffffu, s1, o);
            q1 += __shfl_xor_sync(0xffffffffu, q1, o);
        }
        float mu0 = s0 * (1.f/64.f);
        float iv0 = rsqrtf(fmaf(-mu0, mu0, q0 * (1.f/64.f)) + 1e-6f);
        float mu1 = s1 * (1.f/64.f);
        float iv1 = rsqrtf(fmaf(-mu1, mu1, q1 * (1.f/64.f)) + 1e-6f);

        float* y0 = g_y2 + (size_t)(wr + mt*16)*H2;
        float* y1 = y0 + (size_t)8*H2;
#pragma unroll
        for (int nt = 0; nt < 8; nt++) {
            int c0 = nt*8 + 2*q;
            float2 o0, o1;
            o0.x = (d[mt][nt][0] - mu0)*iv0*lss[c0]     + lbs[c0];
            o0.y = (d[mt][nt][1] - mu0)*iv0*lss[c0 + 1] + lbs[c0 + 1];
            o1.x = (d[mt][nt][2] - mu1)*iv1*lss[c0]     + lbs[c0];
            o1.y = (d[mt][nt][3] - mu1)*iv1*lss[c0 + 1] + lbs[c0 + 1];
            *(float2*)(y0 + c0) = o0;
            *(float2*)(y1 + c0) = o1;
        }
    }
}

// ---------------- K4: LIF scan layer 2, 8-way T-chunked (warmup 64) ----------
__global__ void __launch_bounds__(256) k4_lif2(const float* __restrict__ decay)
{
    int gt = blockIdx.x*256 + threadIdx.x;
    int gw = gt >> 5, lane = gt & 31;
    int chunk = gw & 7;
    int kb = (gw >> 3) & 1;
    int b = gw >> 4;
    int k = (kb << 5) + lane;
    float d = 1.f / (1.f + expf(-decay[k]));
    const int t0 = chunk*125;
    const float* xp = g_y2 + (size_t)b*TT*H2 + k;
    unsigned* sp = g_spk2 + (size_t)b*TT*2 + kb + (size_t)t0*2;
    unsigned cnt;
    if (chunk == 0)
        cnt = lif_chunk<125, 0>(xp, sp, d, lane, H2, 2);
    else
        cnt = lif_chunk<189, 64>(xp + (size_t)(t0 - 64)*H2, sp, d, lane, H2, 2);
    if (lane == 0) atomicAdd(&g_cnt2, cnt);
}

// ---------------- K5: logits + softmax + pool + output (merged) --------------
__global__ void __launch_bounds__(256) k5b(const float* __restrict__ Wa,
                                           const float* __restrict__ ba,
                                           const float* __restrict__ Wo,
                                           const float* __restrict__ bo,
                                           float* __restrict__ out, int rate_idx)
{
    __shared__ float was[H2];
    __shared__ float es[TT];
    __shared__ uint2 sspk[TT];
    __shared__ float red[8];
    __shared__ float bcM, bcS;
    __shared__ float fpart[4][H2];
    __shared__ float featS[H2];
    int b = blockIdx.x, tid = threadIdx.x;
    int warp = tid >> 5, lane = tid & 31;
    const unsigned* spb = g_spk2 + (size_t)b*TT*2;

    if (tid < H2) was[tid] = Wa[tid];
    __syncthreads();
    const float ba0 = ba[0];

    float lm = -3.402823466e38f;
    for (int t = tid; t < TT; t += 256) {
        uint2 m = *(const uint2*)(spb + (size_t)t*2);
        sspk[t] = m;
        float av = ba0;
        unsigned mm = m.x;
        while (mm) { av += was[__ffs(mm) - 1];      mm &= mm - 1; }
        mm = m.y;
        while (mm) { av += was[32 + __ffs(mm) - 1]; mm &= mm - 1; }
        es[t] = av;
        lm = fmaxf(lm, av);
    }
#pragma unroll
    for (int o = 16; o > 0; o >>= 1) lm = fmaxf(lm, __shfl_xor_sync(0xffffffffu, lm, o));
    if (lane == 0) red[warp] = lm;
    __syncthreads();
    if (tid == 0) {
        float m = red[0];
#pragma unroll
        for (int w = 1; w < 8; w++) m = fmaxf(m, red[w]);
        bcM = m;
    }
    __syncthreads();
    float M = bcM;
    float ls = 0.f;
    for (int t = tid; t < TT; t += 256) { float e = expf(es[t] - M); es[t] = e; ls += e; }
#pragma unroll
    for (int o = 16; o > 0; o >>= 1) ls += __shfl_xor_sync(0xffffffffu, ls, o);
    if (lane == 0) red[warp] = ls;
    __syncthreads();
    if (tid == 0) {
        float sm = 0.f;
#pragma unroll
        for (int w = 0; w < 8; w++) sm += red[w];
        bcS = sm;
    }
    __syncthreads();
    float S = bcS;

    {
        int col = tid & 63, qt = tid >> 6;
        unsigned bit = 1u << (col & 31);
        bool hi = (col >> 5) & 1;
        float acc = 0.f;
        int t0 = qt*250, t1 = t0 + 250;
        for (int t = t0; t < t1; t++) {
            uint2 m = sspk[t];
            unsigned w = hi ? m.y : m.x;
            if (w & bit) acc += es[t];
        }
        fpart[qt][col] = acc;
    }
    __syncthreads();
    if (tid < H2)
        featS[tid] = (fpart[0][tid] + fpart[1][tid] + fpart[2][tid] + fpart[3][tid]) / S;
    __syncthreads();
    if (tid < NC) {
        float l = bo[tid];
#pragma unroll
        for (int k = 0; k < H2; k++) l = fmaf(featS[k], Wo[k*NC + tid], l);
        out[b*NC + tid] = l;
    }
    if (b == 0 && tid == 0) {
        float r1 = (float)g_cnt1 / (float)((size_t)BT * H1);
        float r2 = (float)g_cnt2 / (float)((size_t)BT * H2);
        out[rate_idx] = 0.5f * (r1 + r2);
    }
}

// ---------------- launch ----------------
extern "C" void kernel_launch(void* const* d_in, const int* in_sizes, int n_in,
                              void* d_out, int out_size)
{
    const float* x   = (const float*)d_in[0];
    const float* W1  = (const float*)d_in[1];
    const float* b1  = (const float*)d_in[2];
    const float* l1s = (const float*)d_in[3];
    const float* l1b = (const float*)d_in[4];
    const float* dc1 = (const float*)d_in[5];
    const float* W2  = (const float*)d_in[6];
    const float* b2  = (const float*)d_in[7];
    const float* l2s = (const float*)d_in[8];
    const float* l2b = (const float*)d_in[9];
    const float* dc2 = (const float*)d_in[10];
    const float* Wa  = (const float*)d_in[11];
    const float* ba  = (const float*)d_in[12];
    const float* Wo  = (const float*)d_in[13];
    const float* bo  = (const float*)d_in[14];
    float* out = (float*)d_out;

    cudaFuncSetAttribute(k1_gemm1, cudaFuncAttributeMaxDynamicSharedMemorySize, K1_SMEM);
    cudaFuncSetAttribute(k3_gemm2, cudaFuncAttributeMaxDynamicSharedMemorySize, K3_SMEM);

    // k1 at position 4 for the fixed ncu capture window
    k0_prep<<<132, 256>>>(W1, W2);
    k0n_nop<<<1, 32>>>();
    k0n_nop<<<1, 32>>>();
    k1_gemm1<<<BT/64, 256, K1_SMEM>>>(x, b1, l1s, l1b);
    k2_lif1<<<(BB*H1*8)/256, 256>>>(dc1);
    k3_gemm2<<<BT/256, 256, K3_SMEM>>>(b2, l2s, l2b);
    k4_lif2<<<(BB*H2*8)/256, 256>>>(dc2);
    k5b<<<BB, 256>>>(Wa, ba, Wo, bo, out, out_size - 1);
}